// round 5
// baseline (speedup 1.0000x reference)
#include <cuda_runtime.h>
#include <cuda_bf16.h>
#include <cstdint>

#define BATCH 64
#define SEQ   512
#define DIN   512
#define MEM   256
#define HID   512

// ---------------- scratch ----------------
__device__ float g_u[BATCH * SEQ];
__device__ float g_H[MEM * SEQ];
__device__ float g_P[2][MEM * MEM];
__device__ float g_m[(size_t)BATCH * SEQ * MEM];

// ---------------- helpers ----------------
__device__ __forceinline__ uint32_t f2tf(float x) {
    uint32_t r;
    asm("cvt.rna.tf32.f32 %0, %1;" : "=r"(r) : "f"(x));
    return r;
}
__device__ __forceinline__ void mma_tf32(float* d, const uint32_t* a,
                                         const uint32_t* b, const float* c) {
    asm volatile(
        "mma.sync.aligned.m16n8k8.row.col.f32.tf32.tf32.f32 "
        "{%0,%1,%2,%3}, {%4,%5,%6,%7}, {%8,%9}, {%10,%11,%12,%13};\n"
        : "=f"(d[0]), "=f"(d[1]), "=f"(d[2]), "=f"(d[3])
        : "r"(a[0]), "r"(a[1]), "r"(a[2]), "r"(a[3]),
          "r"(b[0]), "r"(b[1]),
          "f"(c[0]), "f"(c[1]), "f"(c[2]), "f"(c[3]));
}

// ---------------- kernel 0: init ----------------
__global__ void k_init(const float* __restrict__ A, const float* __restrict__ B) {
    int i = blockIdx.x * 256 + threadIdx.x;
    g_P[0][i] = A[i];
    if (i < MEM) g_H[i * SEQ] = B[i];
}

// ---------------- kernel 1: u projection ----------------
__global__ void k_u(const float* __restrict__ x, const float* __restrict__ w,
                    const float* __restrict__ bptr, float* __restrict__ u) {
    __shared__ __align__(16) float ws[DIN];
    int tid = threadIdx.x;
    ws[tid] = w[tid];
    ws[tid + 256] = w[tid + 256];
    __syncthreads();
    int warp = tid >> 5, lane = tid & 31;
    int row = blockIdx.x * 8 + warp;
    const float4* x4 = (const float4*)(x + (size_t)row * DIN);
    const float4* w4 = (const float4*)ws;
    float s = 0.f;
#pragma unroll
    for (int i = lane; i < DIN / 4; i += 32) {
        float4 xv = x4[i];
        float4 wv = w4[i];
        s += xv.x * wv.x + xv.y * wv.y + xv.z * wv.z + xv.w * wv.w;
    }
#pragma unroll
    for (int o = 16; o > 0; o >>= 1) s += __shfl_xor_sync(0xffffffffu, s, o);
    if (lane == 0) u[row] = fmaxf(s + bptr[0], 0.f);
}

// ---------------- kernel 2: fused doubling stage (fp32) ----------------
// z=0: H[:, len:2len] = P @ H[:, 0:len]   (ld 512)
// z=1: Pout = P @ P                        (ld 256, only if doP2)
__global__ void k_stage(const float* __restrict__ P, float* __restrict__ H,
                        int len, float* __restrict__ Pout, int doP2) {
    const float* S;
    float* C;
    int ldS, ldC, N;
    if (blockIdx.z == 0) {
        S = H; ldS = SEQ; C = H + len; ldC = SEQ; N = len;
    } else {
        if (!doP2) return;
        S = P; ldS = MEM; C = Pout; ldC = MEM; N = MEM;
    }
    int c0 = blockIdx.x * 32;
    if (c0 >= N) return;
    __shared__ float Ps[32][33];
    __shared__ float Ss[32][33];
    int tx = threadIdx.x & 15, ty = threadIdx.x >> 4;
    int i0 = blockIdx.y * 32;
    float acc00 = 0, acc01 = 0, acc10 = 0, acc11 = 0;
    for (int k0 = 0; k0 < 256; k0 += 32) {
#pragma unroll
        for (int l = 0; l < 4; l++) {
            int idx = threadIdx.x + l * 256;
            int r = idx >> 5, cc = idx & 31;
            Ps[r][cc] = P[(i0 + r) * 256 + k0 + cc];
            int c = c0 + cc;
            Ss[r][cc] = (c < N) ? S[(size_t)(k0 + r) * ldS + c] : 0.f;
        }
        __syncthreads();
#pragma unroll
        for (int k = 0; k < 32; k++) {
            float a0 = Ps[ty * 2][k], a1 = Ps[ty * 2 + 1][k];
            float b0 = Ss[k][tx * 2], b1 = Ss[k][tx * 2 + 1];
            acc00 += a0 * b0; acc01 += a0 * b1;
            acc10 += a1 * b0; acc11 += a1 * b1;
        }
        __syncthreads();
    }
    int i = i0 + ty * 2, c = c0 + tx * 2;
    if (c < N)     { C[(size_t)i * ldC + c] = acc00; C[(size_t)(i + 1) * ldC + c] = acc10; }
    if (c + 1 < N) { C[(size_t)i * ldC + c + 1] = acc01; C[(size_t)(i + 1) * ldC + c + 1] = acc11; }
}

// ---------------- kernel 3: causal conv, tf32 tensor cores ----------------
// m[b,t,k] = sum_d H[k,d] u[b,t-d].  Per block: 64(t) x 64(k) tile.
// A[t,d] = u[t-d] (row-major Toeplitz from smem), B[d,k] = H[k,d] (col-major frag).
__global__ __launch_bounds__(128) void k_conv(const float* __restrict__ u,
                                              float* __restrict__ mm) {
    __shared__ uint32_t us[128];
    __shared__ uint32_t Hs[64][68];
    int b = blockIdx.z;
    int t0 = blockIdx.y * 64;
    int k0 = blockIdx.x * 64;
    int tid = threadIdx.x;
    int lane = tid & 31, wid = tid >> 5;
    int wm = (wid & 1) * 32, wn = (wid >> 1) * 32;
    int lp = lane >> 2, lq = lane & 3;
    const float* urow = u + b * SEQ;

    float acc[2][4][4] = {};
    int ndc = blockIdx.y + 1;
    for (int dc = 0; dc < ndc; dc++) {
        int d0 = dc * 64;
        {
            int idx = t0 - d0 - 63 + tid;
            us[tid] = f2tf((idx >= 0 && idx < SEQ) ? urow[idx] : 0.f);
        }
        {
            int hr = tid >> 1;
            int hc0 = (tid & 1) * 32;
            const float4* hrow = (const float4*)(g_H + (size_t)(k0 + hr) * SEQ + d0 + hc0);
#pragma unroll
            for (int j = 0; j < 8; j++) {
                float4 v = hrow[j];
                Hs[hr][hc0 + j * 4 + 0] = f2tf(v.x);
                Hs[hr][hc0 + j * 4 + 1] = f2tf(v.y);
                Hs[hr][hc0 + j * 4 + 2] = f2tf(v.z);
                Hs[hr][hc0 + j * 4 + 3] = f2tf(v.w);
            }
        }
        __syncthreads();
#pragma unroll
        for (int ds = 0; ds < 8; ds++) {
            int d8 = ds * 8;
            uint32_t af[2][4], bf[4][2];
#pragma unroll
            for (int mb = 0; mb < 2; mb++) {
                int base = wm + mb * 16 + lp + 63 - d8 - lq;
                af[mb][0] = us[base];
                af[mb][1] = us[base + 8];
                af[mb][2] = us[base - 4];
                af[mb][3] = us[base + 4];
            }
#pragma unroll
            for (int nb = 0; nb < 4; nb++) {
                bf[nb][0] = Hs[wn + nb * 8 + lp][d8 + lq];
                bf[nb][1] = Hs[wn + nb * 8 + lp][d8 + lq + 4];
            }
#pragma unroll
            for (int mb = 0; mb < 2; mb++)
#pragma unroll
                for (int nb = 0; nb < 4; nb++)
                    mma_tf32(acc[mb][nb], af[mb], bf[nb], acc[mb][nb]);
        }
        __syncthreads();
    }
#pragma unroll
    for (int mb = 0; mb < 2; mb++)
#pragma unroll
        for (int nb = 0; nb < 4; nb++) {
            int t = t0 + wm + mb * 16 + lp;
            int k = k0 + wn + nb * 8 + lq * 2;
            float2 v0 = make_float2(acc[mb][nb][0], acc[mb][nb][1]);
            float2 v1 = make_float2(acc[mb][nb][2], acc[mb][nb][3]);
            *(float2*)&mm[((size_t)b * SEQ + t) * MEM + k] = v0;
            *(float2*)&mm[((size_t)b * SEQ + t + 8) * MEM + k] = v1;
        }
}

// ---------------- kernel 4: h = relu([m|x] @ Wh + b), tf32 tensor cores ----------------
// 32768 x 512, K = 768.  BM=128, BN=128, BK=8, 256 threads (8 warps, 2x4),
// warp tile 64x32, double-buffered smem.
__global__ __launch_bounds__(256) void k_h(const float* __restrict__ mm,
                                           const float* __restrict__ x,
                                           const float* __restrict__ W,
                                           const float* __restrict__ bias,
                                           float* __restrict__ h,
                                           float* __restrict__ hn) {
    __shared__ __align__(16) uint32_t As[2][8][136];
    __shared__ __align__(16) uint32_t Bs[2][8][136];
    int tid = threadIdx.x;
    int lane = tid & 31, wid = tid >> 5;
    int wm = (wid & 1) * 64, wn = (wid >> 1) * 32;
    int lp = lane >> 2, lq = lane & 3;
    int m0 = blockIdx.y * 128, n0 = blockIdx.x * 128;

    int ar = tid >> 1, ak = (tid & 1) * 4;      // A: 128 rows x 8k, 1 float4/thread
    int br = tid >> 5, bn = (tid & 31) * 4;     // B: 8k x 128n, 1 float4/thread
    int arow = m0 + ar;

    float acc[4][4][4] = {};
    float4 va, vb;

    // prologue: tile kt = 0 (k < 256 -> m region)
    va = *(const float4*)(mm + (size_t)arow * MEM + ak);
    vb = *(const float4*)(W + (size_t)br * HID + n0 + bn);
    int buf = 0;
    As[0][ak + 0][ar] = f2tf(va.x); As[0][ak + 1][ar] = f2tf(va.y);
    As[0][ak + 2][ar] = f2tf(va.z); As[0][ak + 3][ar] = f2tf(va.w);
    {
        uint4 t4 = make_uint4(f2tf(vb.x), f2tf(vb.y), f2tf(vb.z), f2tf(vb.w));
        *(uint4*)&Bs[0][br][bn] = t4;
    }
    __syncthreads();

#pragma unroll 1
    for (int kt = 0; kt < MEM + DIN; kt += 8) {
        int nkt = kt + 8;
        if (nkt < MEM + DIN) {
            int k = nkt + ak;
            const float* p = (k < MEM) ? (mm + (size_t)arow * MEM + k)
                                       : (x + (size_t)arow * DIN + (k - MEM));
            va = *(const float4*)p;
            vb = *(const float4*)(W + (size_t)(nkt + br) * HID + n0 + bn);
        }
        // compute on current buffer
        {
            uint32_t af[4][4], bf[4][2];
#pragma unroll
            for (int mb = 0; mb < 4; mb++) {
                int m = wm + mb * 16 + lp;
                af[mb][0] = As[buf][lq][m];
                af[mb][1] = As[buf][lq][m + 8];
                af[mb][2] = As[buf][lq + 4][m];
                af[mb][3] = As[buf][lq + 4][m + 8];
            }
#pragma unroll
            for (int nb = 0; nb < 4; nb++) {
                int n = wn + nb * 8 + lp;
                bf[nb][0] = Bs[buf][lq][n];
                bf[nb][1] = Bs[buf][lq + 4][n];
            }
#pragma unroll
            for (int mb = 0; mb < 4; mb++)
#pragma unroll
                for (int nb = 0; nb < 4; nb++)
                    mma_tf32(acc[mb][nb], af[mb], bf[nb], acc[mb][nb]);
        }
        if (nkt < MEM + DIN) {
            buf ^= 1;
            As[buf][ak + 0][ar] = f2tf(va.x); As[buf][ak + 1][ar] = f2tf(va.y);
            As[buf][ak + 2][ar] = f2tf(va.z); As[buf][ak + 3][ar] = f2tf(va.w);
            uint4 t4 = make_uint4(f2tf(vb.x), f2tf(vb.y), f2tf(vb.z), f2tf(vb.w));
            *(uint4*)&Bs[buf][br][bn] = t4;
            __syncthreads();
        }
    }

    // epilogue: bias + relu + store h (+ h_n for t = SEQ-1 rows)
#pragma unroll
    for (int nb = 0; nb < 4; nb++) {
        int col = n0 + wn + nb * 8 + lq * 2;
        float b0 = bias[col], b1 = bias[col + 1];
#pragma unroll
        for (int mb = 0; mb < 4; mb++) {
            int row0 = m0 + wm + mb * 16 + lp;
            int row1 = row0 + 8;
            float2 v0 = make_float2(fmaxf(acc[mb][nb][0] + b0, 0.f),
                                    fmaxf(acc[mb][nb][1] + b1, 0.f));
            float2 v1 = make_float2(fmaxf(acc[mb][nb][2] + b0, 0.f),
                                    fmaxf(acc[mb][nb][3] + b1, 0.f));
            *(float2*)&h[(size_t)row0 * HID + col] = v0;
            *(float2*)&h[(size_t)row1 * HID + col] = v1;
            if ((row1 & (SEQ - 1)) == SEQ - 1) {
                int bidx = row1 >> 9;
                *(float2*)&hn[(size_t)bidx * HID + col] = v1;
            }
        }
    }
}

// ---------------- launch ----------------
extern "C" void kernel_launch(void* const* d_in, const int* in_sizes, int n_in,
                              void* d_out, int out_size) {
    const float* x    = (const float*)d_in[0];
    const float* Wu_w = (const float*)d_in[1];
    const float* Wu_b = (const float*)d_in[2];
    const float* Wh_w = (const float*)d_in[3];
    const float* Wh_b = (const float*)d_in[4];
    const float* A    = (const float*)d_in[5];
    const float* B    = (const float*)d_in[6];

    float* out = (float*)d_out;
    float* h  = out;
    float* hn = out + (size_t)BATCH * SEQ * HID;

    float *pU, *pH, *pM, *pPbase;
    cudaGetSymbolAddress((void**)&pU, g_u);
    cudaGetSymbolAddress((void**)&pH, g_H);
    cudaGetSymbolAddress((void**)&pM, g_m);
    cudaGetSymbolAddress((void**)&pPbase, g_P);
    float* pP[2] = { pPbase, pPbase + MEM * MEM };

    k_init<<<256, 256>>>(A, B);
    k_u<<<BATCH * SEQ / 8, 256>>>(x, Wu_w, Wu_b, pU);

    // H doubling: 9 fused stages (expansion + P^2 in one launch)
    int cur = 0;
    for (int len = 1; len <= 256; len <<= 1) {
        int doP2 = (len < 256);
        k_stage<<<dim3(8, 8, 2), 256>>>(pP[cur], pH, len, pP[cur ^ 1], doP2);
        if (doP2) cur ^= 1;
    }

    k_conv<<<dim3(MEM / 64, SEQ / 64, BATCH), 128>>>(pU, pM);
    k_h<<<dim3(HID / 128, BATCH * SEQ / 128), 256>>>(pM, x, Wh_w, Wh_b, h, hn);
}